// round 3
// baseline (speedup 1.0000x reference)
#include <cuda_runtime.h>
#include <cstdint>

#define BB 8
#define SS 2048
#define NN 512
#define DD 1024
#define WW 32
#define MASK_FILL (-1000.0f)

#define BIN_SHIFT 6                 // bin width 64 positions
#define NBINS (SS >> BIN_SHIFT)     // 32 bins per batch
#define DSPLIT 4                    // 4 blocks per bin, each 256 floats of D
#define SPAN_THREADS 64             // 64 threads * float4 = 256 floats

// Scratch (allocation-free: __device__ globals)
__device__ float g_logits[BB * SS];
__device__ int   g_sorted[BB * NN];       // span ids (0..NN-1) sorted by bin, per batch
__device__ int   g_binoff[BB * (NBINS + 1)];

// ---------------------------------------------------------------------------
// Kernel 1: logits[b*S+s] = dot(seq[b,s,:], att_w) + att_b
// One warp per row, 8 warps/block.
// ---------------------------------------------------------------------------
__global__ void __launch_bounds__(256) logits_kernel(
    const float* __restrict__ seq,
    const float* __restrict__ att_w,
    const float* __restrict__ att_b)
{
    int gwarp = (blockIdx.x * blockDim.x + threadIdx.x) >> 5;
    int lane  = threadIdx.x & 31;
    if (gwarp >= BB * SS) return;

    const float4* row = reinterpret_cast<const float4*>(seq) + (size_t)gwarp * (DD / 4);
    const float4* wv  = reinterpret_cast<const float4*>(att_w);

    float acc = 0.0f;
#pragma unroll
    for (int i = 0; i < DD / 4 / 32; i++) {
        float4 a = row[lane + 32 * i];
        float4 b = wv [lane + 32 * i];
        acc += a.x * b.x + a.y * b.y + a.z * b.z + a.w * b.w;
    }
#pragma unroll
    for (int o = 16; o; o >>= 1)
        acc += __shfl_xor_sync(0xffffffffu, acc, o);

    if (lane == 0)
        g_logits[gwarp] = acc + att_b[0];
}

// ---------------------------------------------------------------------------
// Kernel 2: counting-sort spans into bins by end>>BIN_SHIFT.
// One block per batch, NN threads (one per span).
// ---------------------------------------------------------------------------
__global__ void __launch_bounds__(NN) bin_kernel(const int* __restrict__ spans)
{
    __shared__ int hist[NBINS];
    __shared__ int offs[NBINS + 1];
    __shared__ int cursor[NBINS];

    const int b   = blockIdx.x;
    const int tid = threadIdx.x;

    if (tid < NBINS) hist[tid] = 0;
    __syncthreads();

    const int end = spans[(b * NN + tid) * 2 + 1];
    const int bin = end >> BIN_SHIFT;
    atomicAdd(&hist[bin], 1);
    __syncthreads();

    if (tid == 0) {
        int run = 0;
#pragma unroll
        for (int k = 0; k < NBINS; k++) { offs[k] = run; run += hist[k]; }
        offs[NBINS] = NN;
    }
    __syncthreads();
    if (tid < NBINS) cursor[tid] = offs[tid];
    __syncthreads();

    int pos = atomicAdd(&cursor[bin], 1);
    g_sorted[b * NN + pos] = tid;

    if (tid <= NBINS) g_binoff[b * (NBINS + 1) + tid] = offs[tid];
}

// ---------------------------------------------------------------------------
// Kernel 3: one block per (bin, D-quarter). Processes all spans of the bin
// sequentially; row gathers hit L1 across spans (footprint <= 95 rows x 1KB).
// Masked positions have attn exactly 0 (expf underflow) -> skipped exactly.
// ---------------------------------------------------------------------------
__global__ void __launch_bounds__(SPAN_THREADS) span_kernel(
    const float* __restrict__ seq,
    const int*   __restrict__ spans,
    float*       __restrict__ out)
{
    const int bing = blockIdx.x >> 2;        // global bin id
    const int dq   = blockIdx.x & 3;         // D quarter
    const int b    = bing >> 5;              // NBINS = 32
    const int lbin = bing & (NBINS - 1);

    const int s0 = g_binoff[b * (NBINS + 1) + lbin];
    const int s1 = g_binoff[b * (NBINS + 1) + lbin + 1];
    if (s0 == s1) return;

    __shared__ float s_attn[WW];
    __shared__ int   s_idx[WW];
    __shared__ int   s_cnt;
    __shared__ int   s_n;

    const int tid = threadIdx.x;
    const float4* bbase = reinterpret_cast<const float4*>(seq)
                        + (size_t)b * SS * (DD / 4) + dq * (DD / 4 / DSPLIT) + tid;
    float4* obase = reinterpret_cast<float4*>(out)
                  + (size_t)b * NN * (DD / 4) + dq * (DD / 4 / DSPLIT) + tid;

    for (int si = s0; si < s1; si++) {
        if (tid < 32) {
            const int n     = g_sorted[b * NN + si];
            const int start = spans[(b * NN + n) * 2 + 0];
            const int end   = spans[(b * NN + n) * 2 + 1];
            const int width = end - start;
            const int w     = tid;
            const int raw   = end - w;
            const bool ok   = (w <= width) && (raw >= 0);
            const int idx   = raw > 0 ? raw : 0;

            float lg = ok ? g_logits[b * SS + idx] : MASK_FILL;

            float m = lg;
#pragma unroll
            for (int o = 16; o; o >>= 1)
                m = fmaxf(m, __shfl_xor_sync(0xffffffffu, m, o));
            float e = __expf(lg - m);
            float sum = e;
#pragma unroll
            for (int o = 16; o; o >>= 1)
                sum += __shfl_xor_sync(0xffffffffu, sum, o);

            s_attn[w] = e / sum;
            s_idx[w]  = idx;
            if (w == 0) {
                int c = width < (WW - 1) ? width : (WW - 1);
                s_cnt = c + 1;
                s_n   = n;
            }
        }
        __syncthreads();

        const int cnt = s_cnt;
        const int n   = s_n;

        float4 acc = make_float4(0.f, 0.f, 0.f, 0.f);
        int w = 0;
        for (; w + 4 <= cnt; w += 4) {
            float a0 = s_attn[w + 0]; int i0 = s_idx[w + 0];
            float a1 = s_attn[w + 1]; int i1 = s_idx[w + 1];
            float a2 = s_attn[w + 2]; int i2 = s_idx[w + 2];
            float a3 = s_attn[w + 3]; int i3 = s_idx[w + 3];
            float4 v0 = bbase[i0 * (DD / 4)];
            float4 v1 = bbase[i1 * (DD / 4)];
            float4 v2 = bbase[i2 * (DD / 4)];
            float4 v3 = bbase[i3 * (DD / 4)];
            acc.x += a0 * v0.x; acc.y += a0 * v0.y; acc.z += a0 * v0.z; acc.w += a0 * v0.w;
            acc.x += a1 * v1.x; acc.y += a1 * v1.y; acc.z += a1 * v1.z; acc.w += a1 * v1.w;
            acc.x += a2 * v2.x; acc.y += a2 * v2.y; acc.z += a2 * v2.z; acc.w += a2 * v2.w;
            acc.x += a3 * v3.x; acc.y += a3 * v3.y; acc.z += a3 * v3.z; acc.w += a3 * v3.w;
        }
        for (; w < cnt; w++) {
            float a  = s_attn[w];
            float4 v = bbase[s_idx[w] * (DD / 4)];
            acc.x += a * v.x; acc.y += a * v.y; acc.z += a * v.z; acc.w += a * v.w;
        }

        obase[(size_t)n * (DD / 4)] = acc;
        __syncthreads();   // protect s_attn/s_idx before next span overwrites
    }
}

// ---------------------------------------------------------------------------
// inputs: [0] sequence_tensor f32 (B,S,D)  [1] span_indices i32 (B,N,2)
//         [2] att_w f32 (D,1)              [3] att_b f32 (1)
// output: f32 (B,N,D)
// ---------------------------------------------------------------------------
extern "C" void kernel_launch(void* const* d_in, const int* in_sizes, int n_in,
                              void* d_out, int out_size)
{
    const float* seq   = (const float*)d_in[0];
    const int*   spans = (const int*)  d_in[1];
    const float* att_w = (const float*)d_in[2];
    const float* att_b = (const float*)d_in[3];
    float*       out   = (float*)d_out;

    (void)in_sizes; (void)n_in; (void)out_size;

    logits_kernel<<<(BB * SS) / 8, 256>>>(seq, att_w, att_b);
    bin_kernel<<<BB, NN>>>(spans);
    span_kernel<<<BB * NBINS * DSPLIT, SPAN_THREADS>>>(seq, spans, out);
}

// round 4
// speedup vs baseline: 1.0331x; 1.0331x over previous
#include <cuda_runtime.h>
#include <cstdint>

#define BB 8
#define SS 2048
#define NN 512
#define DD 1024
#define WW 32
#define MASK_FILL (-1000.0f)

#define BIN_SHIFT 6                 // bin width 64 positions
#define NBINS (SS >> BIN_SHIFT)     // 32 bins per batch
#define DSPLIT 4                    // 4 blocks per bin, each 256 floats of D
#define SPAN_THREADS 64             // 64 threads * float4 = 256 floats

// Scratch (allocation-free: __device__ globals)
__device__ float g_logits[BB * SS];
__device__ int   g_sorted[BB * NN];       // span ids (0..NN-1) sorted by bin, per batch
__device__ int   g_binoff[BB * (NBINS + 1)];

// ---------------------------------------------------------------------------
// Kernel 1: logits[b*S+s] = dot(seq[b,s,:], att_w) + att_b
// One warp per row, 8 warps/block.
// ---------------------------------------------------------------------------
__global__ void __launch_bounds__(256) logits_kernel(
    const float* __restrict__ seq,
    const float* __restrict__ att_w,
    const float* __restrict__ att_b)
{
    int gwarp = (blockIdx.x * blockDim.x + threadIdx.x) >> 5;
    int lane  = threadIdx.x & 31;
    if (gwarp >= BB * SS) return;

    const float4* row = reinterpret_cast<const float4*>(seq) + (size_t)gwarp * (DD / 4);
    const float4* wv  = reinterpret_cast<const float4*>(att_w);

    float acc = 0.0f;
#pragma unroll
    for (int i = 0; i < DD / 4 / 32; i++) {
        float4 a = row[lane + 32 * i];
        float4 b = wv [lane + 32 * i];
        acc += a.x * b.x + a.y * b.y + a.z * b.z + a.w * b.w;
    }
#pragma unroll
    for (int o = 16; o; o >>= 1)
        acc += __shfl_xor_sync(0xffffffffu, acc, o);

    if (lane == 0)
        g_logits[gwarp] = acc + att_b[0];
}

// ---------------------------------------------------------------------------
// Kernel 2: counting-sort spans into bins by end>>BIN_SHIFT.
// One block per batch, NN threads (one per span).
// ---------------------------------------------------------------------------
__global__ void __launch_bounds__(NN) bin_kernel(const int* __restrict__ spans)
{
    __shared__ int hist[NBINS];
    __shared__ int offs[NBINS + 1];
    __shared__ int cursor[NBINS];

    const int b   = blockIdx.x;
    const int tid = threadIdx.x;

    if (tid < NBINS) hist[tid] = 0;
    __syncthreads();

    const int end = spans[(b * NN + tid) * 2 + 1];
    const int bin = end >> BIN_SHIFT;
    atomicAdd(&hist[bin], 1);
    __syncthreads();

    if (tid == 0) {
        int run = 0;
#pragma unroll
        for (int k = 0; k < NBINS; k++) { offs[k] = run; run += hist[k]; }
        offs[NBINS] = NN;
    }
    __syncthreads();
    if (tid < NBINS) cursor[tid] = offs[tid];
    __syncthreads();

    int pos = atomicAdd(&cursor[bin], 1);
    g_sorted[b * NN + pos] = tid;

    if (tid <= NBINS) g_binoff[b * (NBINS + 1) + tid] = offs[tid];
}

// ---------------------------------------------------------------------------
// Kernel 3: one block per (bin, D-quarter). Processes all spans of the bin
// sequentially; row gathers hit L1 across spans (footprint <= 95 rows x 1KB).
// Masked positions have attn exactly 0 (expf underflow) -> skipped exactly.
// ---------------------------------------------------------------------------
__global__ void __launch_bounds__(SPAN_THREADS) span_kernel(
    const float* __restrict__ seq,
    const int*   __restrict__ spans,
    float*       __restrict__ out)
{
    const int bing = blockIdx.x >> 2;        // global bin id
    const int dq   = blockIdx.x & 3;         // D quarter
    const int b    = bing >> 5;              // NBINS = 32
    const int lbin = bing & (NBINS - 1);

    const int s0 = g_binoff[b * (NBINS + 1) + lbin];
    const int s1 = g_binoff[b * (NBINS + 1) + lbin + 1];
    if (s0 == s1) return;

    __shared__ float s_attn[WW];
    __shared__ int   s_idx[WW];
    __shared__ int   s_cnt;
    __shared__ int   s_n;

    const int tid = threadIdx.x;
    const float4* bbase = reinterpret_cast<const float4*>(seq)
                        + (size_t)b * SS * (DD / 4) + dq * (DD / 4 / DSPLIT) + tid;
    float4* obase = reinterpret_cast<float4*>(out)
                  + (size_t)b * NN * (DD / 4) + dq * (DD / 4 / DSPLIT) + tid;

    for (int si = s0; si < s1; si++) {
        if (tid < 32) {
            const int n     = g_sorted[b * NN + si];
            const int start = spans[(b * NN + n) * 2 + 0];
            const int end   = spans[(b * NN + n) * 2 + 1];
            const int width = end - start;
            const int w     = tid;
            const int raw   = end - w;
            const bool ok   = (w <= width) && (raw >= 0);
            const int idx   = raw > 0 ? raw : 0;

            float lg = ok ? g_logits[b * SS + idx] : MASK_FILL;

            float m = lg;
#pragma unroll
            for (int o = 16; o; o >>= 1)
                m = fmaxf(m, __shfl_xor_sync(0xffffffffu, m, o));
            float e = __expf(lg - m);
            float sum = e;
#pragma unroll
            for (int o = 16; o; o >>= 1)
                sum += __shfl_xor_sync(0xffffffffu, sum, o);

            s_attn[w] = e / sum;
            s_idx[w]  = idx;
            if (w == 0) {
                int c = width < (WW - 1) ? width : (WW - 1);
                s_cnt = c + 1;
                s_n   = n;
            }
        }
        __syncthreads();

        const int cnt = s_cnt;
        const int n   = s_n;

        float4 acc = make_float4(0.f, 0.f, 0.f, 0.f);
        int w = 0;
        for (; w + 4 <= cnt; w += 4) {
            float a0 = s_attn[w + 0]; int i0 = s_idx[w + 0];
            float a1 = s_attn[w + 1]; int i1 = s_idx[w + 1];
            float a2 = s_attn[w + 2]; int i2 = s_idx[w + 2];
            float a3 = s_attn[w + 3]; int i3 = s_idx[w + 3];
            float4 v0 = bbase[i0 * (DD / 4)];
            float4 v1 = bbase[i1 * (DD / 4)];
            float4 v2 = bbase[i2 * (DD / 4)];
            float4 v3 = bbase[i3 * (DD / 4)];
            acc.x += a0 * v0.x; acc.y += a0 * v0.y; acc.z += a0 * v0.z; acc.w += a0 * v0.w;
            acc.x += a1 * v1.x; acc.y += a1 * v1.y; acc.z += a1 * v1.z; acc.w += a1 * v1.w;
            acc.x += a2 * v2.x; acc.y += a2 * v2.y; acc.z += a2 * v2.z; acc.w += a2 * v2.w;
            acc.x += a3 * v3.x; acc.y += a3 * v3.y; acc.z += a3 * v3.z; acc.w += a3 * v3.w;
        }
        for (; w < cnt; w++) {
            float a  = s_attn[w];
            float4 v = bbase[s_idx[w] * (DD / 4)];
            acc.x += a * v.x; acc.y += a * v.y; acc.z += a * v.z; acc.w += a * v.w;
        }

        obase[(size_t)n * (DD / 4)] = acc;
        __syncthreads();   // protect s_attn/s_idx before next span overwrites
    }
}

// ---------------------------------------------------------------------------
// inputs: [0] sequence_tensor f32 (B,S,D)  [1] span_indices i32 (B,N,2)
//         [2] att_w f32 (D,1)              [3] att_b f32 (1)
// output: f32 (B,N,D)
// ---------------------------------------------------------------------------
extern "C" void kernel_launch(void* const* d_in, const int* in_sizes, int n_in,
                              void* d_out, int out_size)
{
    const float* seq   = (const float*)d_in[0];
    const int*   spans = (const int*)  d_in[1];
    const float* att_w = (const float*)d_in[2];
    const float* att_b = (const float*)d_in[3];
    float*       out   = (float*)d_out;

    (void)in_sizes; (void)n_in; (void)out_size;

    logits_kernel<<<(BB * SS) / 8, 256>>>(seq, att_w, att_b);
    bin_kernel<<<BB, NN>>>(spans);
    span_kernel<<<BB * NBINS * DSPLIT, SPAN_THREADS>>>(seq, spans, out);
}

// round 5
// speedup vs baseline: 1.1587x; 1.1217x over previous
#include <cuda_runtime.h>
#include <cstdint>

#define BB 8
#define SS 2048
#define NN 512
#define DD 1024
#define WW 32
#define MASK_FILL (-1000.0f)

#define BIN_SHIFT 6                 // bin width 64 end-positions
#define NBINS (SS >> BIN_SHIFT)     // 32 bins per batch
#define DSPLIT 4                    // D split into 4 quarters of 256 floats
#define QF4 (DD / 4 / DSPLIT)       // 64 float4 per quarter-row
#define MAXROWS (64 + WW - 1)       // 95: max rows in a bin window
#define SLOTS 4                     // spans processed concurrently per block
#define SPAN_THREADS (SLOTS * QF4)  // 256

// Scratch (allocation-free: __device__ globals)
__device__ float g_logits[BB * SS];
__device__ int   g_sorted[BB * NN];
__device__ int   g_binoff[BB * (NBINS + 1)];

// ---------------------------------------------------------------------------
// Kernel 1: logits[b*S+s] = dot(seq[b,s,:], att_w) + att_b. One warp per row.
// ---------------------------------------------------------------------------
__global__ void __launch_bounds__(256) logits_kernel(
    const float* __restrict__ seq,
    const float* __restrict__ att_w,
    const float* __restrict__ att_b)
{
    int gwarp = (blockIdx.x * blockDim.x + threadIdx.x) >> 5;
    int lane  = threadIdx.x & 31;
    if (gwarp >= BB * SS) return;

    const float4* row = reinterpret_cast<const float4*>(seq) + (size_t)gwarp * (DD / 4);
    const float4* wv  = reinterpret_cast<const float4*>(att_w);

    float acc = 0.0f;
#pragma unroll
    for (int i = 0; i < DD / 4 / 32; i++) {
        float4 a = row[lane + 32 * i];
        float4 b = wv [lane + 32 * i];
        acc += a.x * b.x + a.y * b.y + a.z * b.z + a.w * b.w;
    }
#pragma unroll
    for (int o = 16; o; o >>= 1)
        acc += __shfl_xor_sync(0xffffffffu, acc, o);

    if (lane == 0)
        g_logits[gwarp] = acc + att_b[0];
}

// ---------------------------------------------------------------------------
// Kernel 2: counting-sort span ids into bins by end >> BIN_SHIFT.
// ---------------------------------------------------------------------------
__global__ void __launch_bounds__(NN) bin_kernel(const int* __restrict__ spans)
{
    __shared__ int hist[NBINS];
    __shared__ int offs[NBINS + 1];
    __shared__ int cursor[NBINS];

    const int b   = blockIdx.x;
    const int tid = threadIdx.x;

    if (tid < NBINS) hist[tid] = 0;
    __syncthreads();

    const int end = spans[(b * NN + tid) * 2 + 1];
    const int bin = end >> BIN_SHIFT;
    atomicAdd(&hist[bin], 1);
    __syncthreads();

    if (tid == 0) {
        int run = 0;
#pragma unroll
        for (int k = 0; k < NBINS; k++) { offs[k] = run; run += hist[k]; }
        offs[NBINS] = NN;
    }
    __syncthreads();
    if (tid < NBINS) cursor[tid] = offs[tid];
    __syncthreads();

    int pos = atomicAdd(&cursor[bin], 1);
    g_sorted[b * NN + pos] = tid;

    if (tid <= NBINS) g_binoff[b * (NBINS + 1) + tid] = offs[tid];
}

// ---------------------------------------------------------------------------
// Kernel 3: one block per (bin, D-quarter).
//  Phase A: stage window rows [bin*64-31, bin*64+63] (quarter slices, <=95KB)
//           into dynamic SMEM once.
//  Phase B: process spans of the bin 4 at a time: 4 softmax warps, then
//           64 threads per span accumulate from SMEM. Masked positions have
//           attn exactly 0 (fp32 expf underflow) and are skipped exactly.
// ---------------------------------------------------------------------------
extern __shared__ float sh_tile[];   // MAXROWS * QF4 float4 = up to 97280 B

__global__ void __launch_bounds__(SPAN_THREADS) span_kernel(
    const float* __restrict__ seq,
    const int*   __restrict__ spans,
    float*       __restrict__ out)
{
    const int bing = blockIdx.x >> 2;        // global bin id
    const int dq   = blockIdx.x & 3;         // D quarter
    const int b    = bing >> 5;              // NBINS = 32
    const int lbin = bing & (NBINS - 1);

    const int s0 = g_binoff[b * (NBINS + 1) + lbin];
    const int s1 = g_binoff[b * (NBINS + 1) + lbin + 1];
    if (s0 == s1) return;

    const int tid  = threadIdx.x;
    const int lane = tid & 31;
    const int warp = tid >> 5;

    // window
    const int lo   = (lbin << BIN_SHIFT) - (WW - 1) > 0 ? (lbin << BIN_SHIFT) - (WW - 1) : 0;
    const int hi   = (lbin << BIN_SHIFT) + 63;          // <= SS-1 always
    const int rows = hi - lo + 1;

    // --- Phase A: stage tile ---
    {
        const float4* gbase = reinterpret_cast<const float4*>(seq)
                            + (size_t)b * SS * (DD / 4) + (size_t)lo * (DD / 4) + dq * QF4;
        float4* sbase = reinterpret_cast<float4*>(sh_tile);
        const int total = rows * QF4;
        for (int m = tid; m < total; m += SPAN_THREADS) {
            const int r = m >> 6;            // QF4 = 64
            const int j = m & 63;
            sbase[m] = gbase[(size_t)r * (DD / 4) + j];
        }
    }

    __shared__ float s_attn[SLOTS][WW];
    __shared__ int   s_row [SLOTS][WW];      // idx - lo
    __shared__ int   s_cnt [SLOTS];
    __shared__ int   s_n   [SLOTS];
    __syncthreads();

    const float4* stile = reinterpret_cast<const float4*>(sh_tile);
    float4* obase = reinterpret_cast<float4*>(out)
                  + (size_t)b * NN * (DD / 4) + dq * QF4;

    for (int si = s0; si < s1; si += SLOTS) {
        // --- softmax for up to SLOTS spans (warps 0..3) ---
        if (warp < SLOTS) {
            const int sg = si + warp;
            if (sg < s1) {
                const int n     = g_sorted[b * NN + sg];
                const int start = spans[(b * NN + n) * 2 + 0];
                const int end   = spans[(b * NN + n) * 2 + 1];
                const int width = end - start;
                const int w     = lane;
                const int raw   = end - w;
                const bool ok   = (w <= width) && (raw >= 0);
                const int idx   = raw > 0 ? raw : 0;

                float lg = ok ? g_logits[b * SS + idx] : MASK_FILL;

                float m = lg;
#pragma unroll
                for (int o = 16; o; o >>= 1)
                    m = fmaxf(m, __shfl_xor_sync(0xffffffffu, m, o));
                float e = __expf(lg - m);
                float sum = e;
#pragma unroll
                for (int o = 16; o; o >>= 1)
                    sum += __shfl_xor_sync(0xffffffffu, sum, o);

                s_attn[warp][w] = e / sum;
                s_row [warp][w] = idx - lo;
                if (w == 0) {
                    int c = width < (WW - 1) ? width : (WW - 1);
                    s_cnt[warp] = c + 1;
                    s_n  [warp] = n;
                }
            } else if (lane == 0) {
                s_cnt[warp] = 0;
            }
        }
        __syncthreads();

        // --- accumulate from SMEM: 64 threads per span slot ---
        {
            const int slot = tid >> 6;
            const int j    = tid & 63;
            const int cnt  = s_cnt[slot];
            if (cnt > 0) {
                float4 acc = make_float4(0.f, 0.f, 0.f, 0.f);
                int w = 0;
                for (; w + 4 <= cnt; w += 4) {
                    float a0 = s_attn[slot][w + 0]; int r0 = s_row[slot][w + 0];
                    float a1 = s_attn[slot][w + 1]; int r1 = s_row[slot][w + 1];
                    float a2 = s_attn[slot][w + 2]; int r2 = s_row[slot][w + 2];
                    float a3 = s_attn[slot][w + 3]; int r3 = s_row[slot][w + 3];
                    float4 v0 = stile[r0 * QF4 + j];
                    float4 v1 = stile[r1 * QF4 + j];
                    float4 v2 = stile[r2 * QF4 + j];
                    float4 v3 = stile[r3 * QF4 + j];
                    acc.x += a0 * v0.x; acc.y += a0 * v0.y; acc.z += a0 * v0.z; acc.w += a0 * v0.w;
                    acc.x += a1 * v1.x; acc.y += a1 * v1.y; acc.z += a1 * v1.z; acc.w += a1 * v1.w;
                    acc.x += a2 * v2.x; acc.y += a2 * v2.y; acc.z += a2 * v2.z; acc.w += a2 * v2.w;
                    acc.x += a3 * v3.x; acc.y += a3 * v3.y; acc.z += a3 * v3.z; acc.w += a3 * v3.w;
                }
                for (; w < cnt; w++) {
                    float a  = s_attn[slot][w];
                    float4 v = stile[s_row[slot][w] * QF4 + j];
                    acc.x += a * v.x; acc.y += a * v.y; acc.z += a * v.z; acc.w += a * v.w;
                }
                obase[(size_t)s_n[slot] * (DD / 4) + j] = acc;
            }
        }
        __syncthreads();   // protect s_attn/s_row before next slot batch
    }
}

// ---------------------------------------------------------------------------
// inputs: [0] sequence_tensor f32 (B,S,D)  [1] span_indices i32 (B,N,2)
//         [2] att_w f32 (D,1)              [3] att_b f32 (1)
// output: f32 (B,N,D)
// ---------------------------------------------------------------------------
extern "C" void kernel_launch(void* const* d_in, const int* in_sizes, int n_in,
                              void* d_out, int out_size)
{
    const float* seq   = (const float*)d_in[0];
    const int*   spans = (const int*)  d_in[1];
    const float* att_w = (const float*)d_in[2];
    const float* att_b = (const float*)d_in[3];
    float*       out   = (float*)d_out;

    (void)in_sizes; (void)n_in; (void)out_size;

    const int smem_bytes = MAXROWS * QF4 * 4 * sizeof(float);   // 97280
    static bool attr_done = false;
    if (!attr_done) {
        cudaFuncSetAttribute(span_kernel,
                             cudaFuncAttributeMaxDynamicSharedMemorySize, smem_bytes);
        attr_done = true;
    }

    logits_kernel<<<(BB * SS) / 8, 256>>>(seq, att_w, att_b);
    bin_kernel<<<BB, NN>>>(spans);
    span_kernel<<<BB * NBINS * DSPLIT, SPAN_THREADS, smem_bytes>>>(seq, spans, out);
}